// round 6
// baseline (speedup 1.0000x reference)
#include <cuda_runtime.h>

// LearnableConvCensus: depthwise 3x3 conv (multiplier 8) -> sigmoid -> mean over 8.
// B=4, C=64, H=W=256, pad=1.
//
// sigmoid(z) = 0.5 + 0.5*tanh(z/2); fold 0.5*temperature[c] into pre-scaled
// weights/bias. out = 0.5 + (sum_m tanh_m) / 16.
//
// R6: phase loop (fine MUFU spread) + window-level software pipeline (next
// row's LDS issued after phase 0, hidden under phases 1-3) + FFMA-imm (rt=1)
// for the tanh-sum accumulation to cut FMA-pipe demand 360->324 cyc/row.

#define B_ 4
#define C_ 64
#define H_ 256
#define W_ 256
#define R_ 32                 // output rows per block
#define NROWS (R_ + 2)        // tile rows incl. halo
#define SROW 264              // smem row stride in floats

typedef unsigned long long ull;

__device__ __forceinline__ ull pack2(float lo, float hi) {
    ull r;
    asm("mov.b64 %0, {%1, %2};" : "=l"(r) : "f"(lo), "f"(hi));
    return r;
}
__device__ __forceinline__ ull dup2(float v) {
    ull r;
    asm("mov.b64 %0, {%1, %1};" : "=l"(r) : "f"(v));
    return r;
}
__device__ __forceinline__ void unpack2(ull v, float& lo, float& hi) {
    asm("mov.b64 {%0, %1}, %2;" : "=f"(lo), "=f"(hi) : "l"(v));
}
__device__ __forceinline__ void fma2(ull& acc, ull a, ull b) {
    asm("fma.rn.f32x2 %0, %1, %2, %0;" : "+l"(acc) : "l"(a), "l"(b));
}
__device__ __forceinline__ float tanh_fast(float x) {
    float y;
    asm("tanh.approx.f32 %0, %1;" : "=f"(y) : "f"(x));
    return y;
}
// s += t via FFMA-imm (rt_SMSP=1, double the FADD throughput)
__device__ __forceinline__ void acc1(float& s, float t) {
    asm("fma.rn.f32 %0, %1, 0f3F800000, %0;" : "+f"(s) : "f"(t));
}

__global__ __launch_bounds__(128, 4)
void census_kernel(const float* __restrict__ x, const float* __restrict__ w,
                   const float* __restrict__ bias, const float* __restrict__ temp,
                   float* __restrict__ out) {
    __shared__ float smem[NROWS * SROW];
    __shared__ ull   wsm[4][10];    // [pair p][tap k], pre-scaled; [9] pad
    __shared__ ull   bsm[4];        // bias pairs

    const int bid   = blockIdx.x;
    const int strip = bid & 7;          // H_/R_ = 8 strips
    const int c     = (bid >> 3) & 63;
    const int b     = bid >> 9;
    const int h0    = strip * R_;
    const int tid   = threadIdx.x;

    const float* xp = x + ((size_t)(b * C_ + c) * H_) * W_;

    // ---- weight prep: w layout HWIO flattened w[(kh*3+kw)*512 + c*8 + m]
    if (tid < 40) {
        const float sc = 0.5f * __ldg(&temp[c]);
        if (tid < 36) {
            const int k = tid % 9, p = tid / 9;
            const float w0 = __ldg(&w[k * 512 + (c << 3) + 2 * p])     * sc;
            const float w1 = __ldg(&w[k * 512 + (c << 3) + 2 * p + 1]) * sc;
            wsm[p][k] = pack2(w0, w1);
        } else {
            const int p = tid - 36;
            const float b0 = __ldg(&bias[(c << 3) + 2 * p])     * sc;
            const float b1 = __ldg(&bias[(c << 3) + 2 * p + 1]) * sc;
            bsm[p] = pack2(b0, b1);
        }
    }

    // ---- tile load: smem[r][4 + wcol] = x[h0 + r - 1][wcol]; cols 3 & 260 are
    // the zero conv padding (tiles span the full width).
    #pragma unroll
    for (int i = tid; i < NROWS * 64; i += 128) {
        const int r  = i >> 6;
        const int c4 = (i & 63) << 2;
        const int gh = h0 + r - 1;
        float4 v = make_float4(0.f, 0.f, 0.f, 0.f);
        if (gh >= 0 && gh < H_) v = *(const float4*)(xp + gh * W_ + c4);
        *(float4*)&smem[r * SROW + 4 + c4] = v;
    }
    for (int r = tid; r < NROWS; r += 128) {
        smem[r * SROW + 3]   = 0.f;
        smem[r * SROW + 260] = 0.f;
    }
    __syncthreads();

    ull bp[4];
    bp[0] = bsm[0]; bp[1] = bsm[1]; bp[2] = bsm[2]; bp[3] = bsm[3];

    const int tx = tid & 63;   // 64 threads across width, 4 cols each
    const int ty = tid >> 6;   // 2 row-groups
    float* outp = out + (((size_t)(b * C_ + c) * H_) + h0) * W_ + (tx << 2);

    // window load: d[kh][i] = dup(x[rbase+kh-1][4tx-1+i]), i=0..5
    auto loadwin = [&](int rbase, ull (&d)[3][6]) {
        #pragma unroll
        for (int kh = 0; kh < 3; kh++) {
            const float* rowp = &smem[(rbase + kh) * SROW + (tx << 2)];
            const float  wm1 = rowp[3];
            const float4 f4  = *(const float4*)(rowp + 4);
            const float  wp4 = rowp[8];
            d[kh][0] = dup2(wm1);
            d[kh][1] = dup2(f4.x);
            d[kh][2] = dup2(f4.y);
            d[kh][3] = dup2(f4.z);
            d[kh][4] = dup2(f4.w);
            d[kh][5] = dup2(wp4);
        }
    };

    // one multiplier-pair phase: 36 FFMA2 + 8 tanh + 8 FFMA-imm
    auto phase = [&](int p, ull (&d)[3][6], float* s) {
        const ulonglong2 wA = *(const ulonglong2*)&wsm[p][0];  // taps 0,1
        const ulonglong2 wB = *(const ulonglong2*)&wsm[p][2];  // taps 2,3
        const ulonglong2 wC = *(const ulonglong2*)&wsm[p][4];  // taps 4,5
        const ulonglong2 wD = *(const ulonglong2*)&wsm[p][6];  // taps 6,7
        const ull        w8 = wsm[p][8];
        ull a0 = bp[p], a1 = bp[p], a2 = bp[p], a3 = bp[p];
        #define TAP(kh, kw, W) \
            fma2(a0, d[kh][kw + 0], W); fma2(a1, d[kh][kw + 1], W); \
            fma2(a2, d[kh][kw + 2], W); fma2(a3, d[kh][kw + 3], W);
        TAP(0, 0, wA.x)  TAP(0, 1, wA.y)  TAP(0, 2, wB.x)
        TAP(1, 0, wB.y)  TAP(1, 1, wC.x)  TAP(1, 2, wC.y)
        TAP(2, 0, wD.x)  TAP(2, 1, wD.y)  TAP(2, 2, w8)
        #undef TAP
        float v0, v1;
        unpack2(a0, v0, v1); acc1(s[0], tanh_fast(v0)); acc1(s[0], tanh_fast(v1));
        unpack2(a1, v0, v1); acc1(s[1], tanh_fast(v0)); acc1(s[1], tanh_fast(v1));
        unpack2(a2, v0, v1); acc1(s[2], tanh_fast(v0)); acc1(s[2], tanh_fast(v1));
        unpack2(a3, v0, v1); acc1(s[3], tanh_fast(v0)); acc1(s[3], tanh_fast(v1));
    };

    auto store_row = [&](int r, float* s) {
        float4 o;
        o.x = fmaf(s[0], 0.0625f, 0.5f);
        o.y = fmaf(s[1], 0.0625f, 0.5f);
        o.z = fmaf(s[2], 0.0625f, 0.5f);
        o.w = fmaf(s[3], 0.0625f, 0.5f);
        *(float4*)(outp + r * W_) = o;
    };

    ull dA[3][6], dB[3][6];
    loadwin(ty, dA);
    int r = ty;
    #pragma unroll 1
    for (int i = 0; i < 8; i++) {
        {   // row r from dA; prefetch row r+2 into dB under phases 1-3
            float s[4] = {0.f, 0.f, 0.f, 0.f};
            phase(0, dA, s);
            loadwin(r + 2, dB);
            phase(1, dA, s);
            phase(2, dA, s);
            phase(3, dA, s);
            store_row(r, s);
        }
        {   // row r+2 from dB; prefetch row r+4 into dA
            float s[4] = {0.f, 0.f, 0.f, 0.f};
            phase(0, dB, s);
            const int pr = (i < 7) ? (r + 4) : ty;   // last prefetch unused
            loadwin(pr, dA);
            phase(1, dB, s);
            phase(2, dB, s);
            phase(3, dB, s);
            store_row(r + 2, s);
        }
        r += 4;
    }
}

extern "C" void kernel_launch(void* const* d_in, const int* in_sizes, int n_in,
                              void* d_out, int out_size) {
    const float* x    = (const float*)d_in[0];
    const float* w    = (const float*)d_in[1];
    const float* bias = (const float*)d_in[2];
    const float* temp = (const float*)d_in[3];
    float* out = (float*)d_out;

    const int grid = B_ * C_ * (H_ / R_);   // 4*64*8 = 2048 blocks
    census_kernel<<<grid, 128>>>(x, w, bias, temp, out);
}